// round 7
// baseline (speedup 1.0000x reference)
#include <cuda_runtime.h>
#include <math.h>

#define NB 32
#define NNODE 2048
#define TT 96
#define KE 20
#define DNODE 40
#define DH 64
#define DG 16
#define NROWS (NB*NNODE)

// ---------------- scratch ----------
__device__ float g_nv1[NNODE*DNODE];
__device__ float g_nv2[NNODE*DNODE];
__device__ float g_adj[(size_t)NNODE*NNODE];
__device__ int   g_cols[NNODE*KE];
__device__ float g_maskv[NNODE*KE];
__device__ int   g_cnt[NNODE];
__device__ int   g_cnt2[NNODE];
__device__ int   g_ptr[NNODE+1];
__device__ int   g_rsrc[NNODE*KE];
__device__ float g_m[(size_t)NROWS*TT];
__device__ float g_xx[(size_t)NROWS*TT];
__device__ float g_skipA[(size_t)NROWS*TT];
__device__ float g_s1[NROWS];
__device__ float g_xg[(size_t)NROWS*DH];
__device__ float g_h[(size_t)NROWS*DG];
__device__ float g_gate[(size_t)NROWS*DG];
__device__ float g_xgg[(size_t)NROWS*DG];
__device__ float g_xx2[(size_t)NROWS*TT];
__device__ float g_part[2048];
__device__ float g_mu[NB];
__device__ float g_rstd[NB];

// ---------------- XLA EmitTanh f32: rational, clamp +-7.99881172180175781 ----
__device__ __forceinline__ float xtanh(float x){
  const float kClamp = 7.99881172180175781f;
  float xc = fminf(fmaxf(x, -kClamp), kClamp);
  float x2 = xc*xc;
  float p = fmaf(x2, -2.76076847742355e-16f, 2.00018790482477e-13f);
  p = fmaf(x2, p, -8.60467152213735e-11f);
  p = fmaf(x2, p,  5.12229709037114e-08f);
  p = fmaf(x2, p,  1.48572235717979e-05f);
  p = fmaf(x2, p,  6.37261928875436e-04f);
  p = fmaf(x2, p,  4.89352455891786e-03f);
  p = xc * p;
  float q = fmaf(x2, 1.19825839466702e-06f, 1.18534705686654e-04f);
  q = fmaf(x2, q, 2.26843463243900e-03f);
  q = fmaf(x2, q, 4.89352518554385e-03f);
  return (fabsf(x) < 0.0004f) ? x : (p/q);
}

// ---------------- graph constructor ----
__global__ void k_nv(const float* __restrict__ emb, const float* __restrict__ w,
                     const float* __restrict__ b, int which){
  int idx = blockIdx.x*256 + threadIdx.x;
  if (idx >= NNODE*DNODE) return;
  int i = idx / DNODE, j = idx - i*DNODE;
  const float* e = emb + i*DNODE;
  const float* wr = w + j*DNODE;
  float s = 0.f;
  #pragma unroll
  for (int k=0;k<DNODE;k++) s = fmaf(e[k], wr[k], s);
  float v = xtanh(3.0f*(s + b[j]));
  if (which) g_nv2[idx] = v; else g_nv1[idx] = v;
}

__global__ void k_adj(){
  __shared__ float A1[16][DNODE], A2[16][DNODE], B1[16][DNODE], B2[16][DNODE];
  int i0 = blockIdx.y*16, j0 = blockIdx.x*16;
  int tx = threadIdx.x, ty = threadIdx.y;
  int tid = ty*16+tx;
  for (int idx=tid; idx<16*DNODE; idx+=256){
    int r = idx/DNODE, k = idx - r*DNODE;
    A1[r][k] = g_nv1[(i0+r)*DNODE+k];
    A2[r][k] = g_nv2[(i0+r)*DNODE+k];
    B1[r][k] = g_nv1[(j0+r)*DNODE+k];
    B2[r][k] = g_nv2[(j0+r)*DNODE+k];
  }
  __syncthreads();
  float p=0.f, q=0.f;
  #pragma unroll
  for (int k=0;k<DNODE;k++){
    p = fmaf(A1[ty][k], B2[tx][k], p);
    q = fmaf(A2[ty][k], B1[tx][k], q);
  }
  float t = xtanh(3.0f*(p-q));
  g_adj[(size_t)(i0+ty)*NNODE + (j0+tx)] = fmaxf(t, 0.f);
}

// top-k with lax.top_k tie-break (ties -> lowest index)
__global__ void k_topk(){
  __shared__ float sv[NNODE];
  __shared__ unsigned long long red[8];
  const int row = blockIdx.x, tid = threadIdx.x;
  const float* ar = g_adj + (size_t)row*NNODE;
  for (int i=tid;i<NNODE;i+=256) sv[i]=ar[i];
  __syncthreads();
  for (int k=0;k<KE;k++){
    unsigned long long best = 0ull;
    for (int i=tid;i<NNODE;i+=256){
      unsigned int b = __float_as_uint(sv[i]);
      b = (b & 0x80000000u) ? ~b : (b | 0x80000000u);
      unsigned long long key = ((unsigned long long)b<<32) | (unsigned int)(NNODE-1-i);
      if (key > best) best = key;
    }
    #pragma unroll
    for (int o=16;o;o>>=1){
      unsigned long long other = __shfl_xor_sync(0xffffffffu, best, o);
      if (other > best) best = other;
    }
    if ((tid&31)==0) red[tid>>5]=best;
    __syncthreads();
    if (tid==0){
      unsigned long long bb=red[0];
      #pragma unroll
      for (int i=1;i<8;i++) if (red[i]>bb) bb=red[i];
      int idx = NNODE-1-(int)(bb & 0xffffffffull);
      float v = sv[idx];
      g_cols[row*KE+k]  = idx;
      g_maskv[row*KE+k] = (v > 0.f) ? 1.f : 0.f;
      sv[idx] = -3.0e38f;
    }
    __syncthreads();
  }
}

// ---------------- reverse CSR ----
__global__ void k_zero(){
  int i = blockIdx.x*256+threadIdx.x;
  if (i < NNODE){ g_cnt[i]=0; g_cnt2[i]=0; }
}
__global__ void k_count(){
  int idx = blockIdx.x*256+threadIdx.x;
  if (idx >= NNODE*KE) return;
  if (g_maskv[idx] > 0.f) atomicAdd(&g_cnt[g_cols[idx]], 1);
}
__global__ void k_scan(){
  __shared__ int s0[NNODE], s1b[NNODE];
  int t = threadIdx.x;
  s0[t] = g_cnt[t]; s0[t+1024] = g_cnt[t+1024];
  __syncthreads();
  int* src = s0; int* dst = s1b;
  for (int off=1; off<NNODE; off<<=1){
    for (int i=t; i<NNODE; i+=1024){
      int v = src[i];
      if (i >= off) v += src[i-off];
      dst[i] = v;
    }
    __syncthreads();
    int* tmp = src; src = dst; dst = tmp;
  }
  if (t==0) g_ptr[0]=0;
  g_ptr[t+1] = src[t];
  g_ptr[t+1024+1] = src[t+1024];
}
__global__ void k_fill(){
  int idx = blockIdx.x*256+threadIdx.x;
  if (idx >= NNODE*KE) return;
  if (g_maskv[idx] > 0.f){
    int n = idx/KE;
    int c = g_cols[idx];
    int s = atomicAdd(&g_cnt2[c], 1);
    g_rsrc[g_ptr[c]+s] = n;
  }
}

// ---------------- decomposition: m = ma1+ma2 ----
__global__ void k_decomp(const float* __restrict__ x){
  __shared__ float sx[4][TT], sst[4][TT];
  int ty = threadIdx.y, t = threadIdx.x;
  size_t r = (size_t)blockIdx.x*4 + ty;
  sx[ty][t] = x[r*TT + t];
  __syncthreads();
  float s = 0.f;
  #pragma unroll
  for (int d=-12; d<=12; d++){
    int j = t+d; j = max(0, min(TT-1, j));
    s += sx[ty][j];
  }
  float ma1 = s / 25.0f;
  sst[ty][t] = sx[ty][t] - ma1;
  __syncthreads();
  s = 0.f;
  #pragma unroll
  for (int d=-12; d<=12; d++){
    int j = t+d; j = max(0, min(TT-1, j));
    s += sst[ty][j];
  }
  g_m[r*TT + t] = ma1 + s / 25.0f;
}

// ---------------- fused GEMM1: xx = (x-m)@Ws^T + m@Wt^T + b ; skipA = x@W0^T + b0
__global__ void __launch_bounds__(256) k_gemm1(
    const float* __restrict__ x,  const float* __restrict__ w0, const float* __restrict__ b0,
    const float* __restrict__ ws, const float* __restrict__ bs,
    const float* __restrict__ wt, const float* __restrict__ bt){
  extern __shared__ float sm[];
  float* sX  = sm;              // x
  float* sS  = sX  + 64*97;     // x - m   (seasonal)
  float* sM  = sS  + 64*97;     // m       (trend)
  float* sWs = sM  + 64*97;
  float* sWt = sWs + 96*97;
  float* sW0 = sWt + 96*97;
  const int tid = threadIdx.x;
  const int row0 = blockIdx.x*64;
  for (int i=tid;i<64*96;i+=256){
    int r=i/96, c=i-r*96;
    size_t g = (size_t)(row0+r)*96 + c;
    float xv = x[g], mv = g_m[g];
    sX[r*97+c] = xv;
    sS[r*97+c] = xv - mv;
    sM[r*97+c] = mv;
  }
  for (int i=tid;i<96*96;i+=256){
    int r=i/96, c=i-r*96;
    sWs[r*97+c] = ws[i];
    sWt[r*97+c] = wt[i];
    sW0[r*97+c] = w0[i];
  }
  __syncthreads();
  const int cx = tid & 15, ry = tid >> 4;
  const float* A   = sX  + ry*4*97;
  const float* S   = sS  + ry*4*97;
  const float* M   = sM  + ry*4*97;
  const float* Wsp = sWs + cx*6*97;
  const float* Wtp = sWt + cx*6*97;
  const float* W0p = sW0 + cx*6*97;
  float aX[24], aS[24];
  #pragma unroll
  for (int i=0;i<24;i++){ aX[i]=0.f; aS[i]=0.f; }
  #pragma unroll 2
  for (int k=0;k<96;k++){
    float xv[4], sv[4], mv[4];
    #pragma unroll
    for (int j=0;j<4;j++){ xv[j]=A[j*97+k]; sv[j]=S[j*97+k]; mv[j]=M[j*97+k]; }
    #pragma unroll
    for (int i=0;i<6;i++){
      float fws=Wsp[i*97+k], fwt=Wtp[i*97+k], fw0=W0p[i*97+k];
      #pragma unroll
      for (int j=0;j<4;j++){
        aX[j*6+i] = fmaf(sv[j], fws, fmaf(mv[j], fwt, aX[j*6+i]));
        aS[j*6+i] = fmaf(xv[j], fw0, aS[j*6+i]);
      }
    }
  }
  #pragma unroll
  for (int j=0;j<4;j++){
    int row = row0 + ry*4 + j;
    #pragma unroll
    for (int i=0;i<6;i++){
      int c = cx*6 + i;
      size_t g = (size_t)row*96 + c;
      g_xx[g]    = aX[j*6+i] + bs[c] + bt[c];
      g_skipA[g] = aS[j*6+i] + b0[c];
    }
  }
}

// ---------------- xg = xx@lin1^T+b ; s1 = xx.skip1+b ----
__global__ void __launch_bounds__(256) k_gemm_xg(
    const float* __restrict__ l1w, const float* __restrict__ l1b,
    const float* __restrict__ s1w, const float* __restrict__ s1b){
  extern __shared__ float sm[];
  float* sA = sm;
  float* sW = sA + 64*97;
  const int tid = threadIdx.x;
  const int row0 = blockIdx.x*64;
  for (int i=tid;i<64*96;i+=256){
    int r=i/96, c=i-r*96;
    sA[r*97+c] = g_xx[(size_t)(row0+r)*96 + c];
    sW[r*97+c] = l1w[i];
  }
  __syncthreads();
  const int cx = tid & 15, ry = tid >> 4;
  const float* A = sA + ry*4*97;
  const float* W = sW + cx*4*97;
  float acc[16];
  #pragma unroll
  for (int i=0;i<16;i++) acc[i]=0.f;
  #pragma unroll 2
  for (int k=0;k<96;k++){
    float a[4];
    #pragma unroll
    for (int j=0;j<4;j++) a[j]=A[j*97+k];
    #pragma unroll
    for (int i=0;i<4;i++){
      float w = W[i*97+k];
      #pragma unroll
      for (int j=0;j<4;j++) acc[j*4+i] = fmaf(a[j], w, acc[j*4+i]);
    }
  }
  #pragma unroll
  for (int j=0;j<4;j++){
    int row = row0 + ry*4 + j;
    #pragma unroll
    for (int i=0;i<4;i++){
      g_xg[(size_t)row*DH + cx*4+i] = acc[j*4+i] + l1b[cx*4+i];
    }
  }
  if (tid < 64){
    float s = 0.f;
    #pragma unroll 4
    for (int k=0;k<96;k++) s = fmaf(sA[tid*97+k], s1w[k], s);
    g_s1[row0+tid] = s + s1b[0];
  }
}

// ---------------- h, gate ----
__global__ void __launch_bounds__(256) k_hg(
    const float* __restrict__ msgw, const float* __restrict__ msgb,
    const float* __restrict__ gatew, const float* __restrict__ gateb){
  __shared__ float sxg[8][DH];
  __shared__ float sW[2*DG*DH];   // msg then gate
  const int tid = threadIdx.x;
  const int row0 = blockIdx.x*8;
  for (int i=tid;i<8*DH;i+=256)
    sxg[i>>6][i&63] = g_xg[(size_t)row0*DH + i];
  for (int i=tid;i<DG*DH;i+=256){
    sW[i] = msgw[i];
    sW[DG*DH + i] = gatew[i];
  }
  __syncthreads();
  int rl = tid >> 5, lane = tid & 31;
  int dd = lane & 15;
  bool isg = lane >= 16;
  const float* W = sW + (isg ? DG*DH : 0) + dd*DH;
  float acc = 0.f;
  #pragma unroll 8
  for (int k=0;k<DH;k++) acc = fmaf(sxg[rl][k], W[k], acc);
  acc += (isg ? gateb[dd] : msgb[dd]);
  size_t o = (size_t)(row0+rl)*DG + dd;
  if (isg) g_gate[o] = 1.f/(1.f+expf(-acc));
  else     g_h[o] = acc;
}

// ---------------- gated aggregation ----
__global__ void k_agg(){
  int b = blockIdx.y;
  int n = blockIdx.x*16 + (threadIdx.x>>4);
  int d = threadIdx.x & 15;
  const float* hb = g_h + (size_t)b*NNODE*DG;
  float acc = 0.f;
  int base = n*KE;
  #pragma unroll
  for (int k=0;k<KE;k++){
    if (g_maskv[base+k] > 0.f) acc += hb[(size_t)g_cols[base+k]*DG + d];
  }
  int e0 = g_ptr[n], e1 = g_ptr[n+1];
  for (int e=e0; e<e1; e++) acc += hb[(size_t)g_rsrc[e]*DG + d];
  size_t idx = ((size_t)b*NNODE + n)*DG + d;
  g_xgg[idx] = g_gate[idx]*acc;
}

// ---------------- xx2 = xgg@lin2^T+b+residual; partial stats ----
__global__ void __launch_bounds__(256) k_gemm_lin2(
    const float* __restrict__ l2w, const float* __restrict__ l2b,
    const float* __restrict__ xin){
  __shared__ float sA[64*17];
  __shared__ float sW[96*17];
  __shared__ float rb[16];
  const int tid = threadIdx.x;
  const int row0 = blockIdx.x*64;
  for (int i=tid;i<64*16;i+=256)
    sA[(i>>4)*17 + (i&15)] = g_xgg[(size_t)row0*DG + i];
  for (int i=tid;i<96*16;i+=256)
    sW[(i>>4)*17 + (i&15)] = l2w[i];
  __syncthreads();
  const int cx = tid & 15, ry = tid >> 4;
  float acc[24];
  #pragma unroll
  for (int i=0;i<24;i++) acc[i]=0.f;
  #pragma unroll
  for (int k=0;k<16;k++){
    float a[4];
    #pragma unroll
    for (int j=0;j<4;j++) a[j]=sA[(ry*4+j)*17+k];
    #pragma unroll
    for (int i=0;i<6;i++){
      float w = sW[(cx*6+i)*17+k];
      #pragma unroll
      for (int j=0;j<4;j++) acc[j*6+i] = fmaf(a[j], w, acc[j*6+i]);
    }
  }
  float ls=0.f, ls2=0.f;
  #pragma unroll
  for (int j=0;j<4;j++){
    int row = row0 + ry*4 + j;
    #pragma unroll
    for (int i=0;i<6;i++){
      int c = cx*6 + i;
      size_t g = (size_t)row*96 + c;
      float v = acc[j*6+i] + l2b[c] + xin[g];
      g_xx2[g] = v;
      ls += v; ls2 = fmaf(v, v, ls2);
    }
  }
  #pragma unroll
  for (int o=16;o;o>>=1){
    ls  += __shfl_xor_sync(0xffffffffu, ls,  o);
    ls2 += __shfl_xor_sync(0xffffffffu, ls2, o);
  }
  int warp = tid>>5, lane = tid&31;
  if (lane==0){ rb[warp]=ls; rb[8+warp]=ls2; }
  __syncthreads();
  if (tid==0){
    float s=0.f, s2=0.f;
    #pragma unroll
    for (int i=0;i<8;i++){ s+=rb[i]; s2+=rb[8+i]; }
    g_part[blockIdx.x*2]   = s;
    g_part[blockIdx.x*2+1] = s2;
  }
}

__global__ void k_stats(){
  int t = threadIdx.x;
  int b = t >> 5, j = t & 31;
  float s  = g_part[(b*32+j)*2];
  float s2 = g_part[(b*32+j)*2+1];
  #pragma unroll
  for (int o=16;o;o>>=1){
    s  += __shfl_xor_sync(0xffffffffu, s,  o);
    s2 += __shfl_xor_sync(0xffffffffu, s2, o);
  }
  if (j==0){
    const float inv = 1.f/(float)((size_t)NNODE*TT);
    float mu = s*inv;
    float var = s2*inv - mu*mu;
    g_mu[b] = mu;
    g_rstd[b] = rsqrtf(var + 1e-5f);
  }
}

// ---------------- LN -> e1 GEMM + skip -> relu (into g_skipA) ----
__global__ void __launch_bounds__(256) k_e1(
    const float* __restrict__ e1w, const float* __restrict__ e1b,
    const float* __restrict__ lnw, const float* __restrict__ lnb){
  extern __shared__ float sm[];
  float* sA = sm;            // 64*97
  float* sW = sA + 64*97;    // 96*97
  const int tid = threadIdx.x;
  const int row0 = blockIdx.x*64;
  const int b = row0 >> 11;
  const float mu = g_mu[b], rstd = g_rstd[b];
  for (int i=tid;i<64*96;i+=256){
    int r=i/96, c=i-r*96;
    int row = row0+r; int n = row & (NNODE-1);
    float v = g_xx2[(size_t)row*96+c];
    sA[r*97+c] = fmaf((v-mu)*rstd, lnw[n*96+c], lnb[n*96+c]);
  }
  for (int i=tid;i<96*96;i+=256){
    int r=i/96, c=i-r*96;
    sW[r*97+c] = e1w[i];
  }
  __syncthreads();
  const int cx = tid & 15, ry = tid >> 4;
  const float* A = sA + ry*4*97;
  const float* W = sW + cx*6*97;
  float acc[24];
  #pragma unroll
  for (int i=0;i<24;i++) acc[i]=0.f;
  #pragma unroll 2
  for (int k=0;k<96;k++){
    float a[4];
    #pragma unroll
    for (int j=0;j<4;j++) a[j]=A[j*97+k];
    #pragma unroll
    for (int i=0;i<6;i++){
      float w = W[i*97+k];
      #pragma unroll
      for (int j=0;j<4;j++) acc[j*6+i] = fmaf(a[j], w, acc[j*6+i]);
    }
  }
  #pragma unroll
  for (int j=0;j<4;j++){
    int row = row0 + ry*4 + j;
    float s1v = g_s1[row];
    #pragma unroll
    for (int i=0;i<6;i++){
      int c = cx*6 + i;
      size_t g = (size_t)row*96 + c;
      float v = acc[j*6+i] + e1b[c] + g_skipA[g] + s1v;
      g_skipA[g] = fmaxf(v, 0.f);
    }
  }
}

// ---------------- relu(A@l3^T+b3) . l4w + l4b -> out ----
__global__ void __launch_bounds__(256) k_l34(
    const float* __restrict__ l3w, const float* __restrict__ l3b,
    const float* __restrict__ l4w, const float* __restrict__ l4b,
    float* __restrict__ out){
  extern __shared__ float sm[];
  float* sA = sm;            // 64*97
  float* sW = sA + 64*97;    // 64*97
  const int tid = threadIdx.x;
  const int row0 = blockIdx.x*64;
  for (int i=tid;i<64*96;i+=256){
    int r=i/96, c=i-r*96;
    sA[r*97+c] = g_skipA[(size_t)(row0+r)*96 + c];
    sW[r*97+c] = l3w[i];
  }
  __syncthreads();
  const int cx = tid & 15, ry = tid >> 4;
  const float* A = sA + ry*4*97;
  const float* W = sW + cx*4*97;
  float acc[16];
  #pragma unroll
  for (int i=0;i<16;i++) acc[i]=0.f;
  #pragma unroll 2
  for (int k=0;k<96;k++){
    float a[4];
    #pragma unroll
    for (int j=0;j<4;j++) a[j]=A[j*97+k];
    #pragma unroll
    for (int i=0;i<4;i++){
      float w = W[i*97+k];
      #pragma unroll
      for (int j=0;j<4;j++) acc[j*4+i] = fmaf(a[j], w, acc[j*4+i]);
    }
  }
  float part[4];
  #pragma unroll
  for (int j=0;j<4;j++){
    float s = 0.f;
    #pragma unroll
    for (int i=0;i<4;i++){
      int c = cx*4 + i;
      float y = fmaxf(acc[j*4+i] + l3b[c], 0.f);
      s = fmaf(y, l4w[c], s);
    }
    part[j] = s;
  }
  #pragma unroll
  for (int j=0;j<4;j++){
    #pragma unroll
    for (int o=8;o;o>>=1) part[j] += __shfl_xor_sync(0xffffffffu, part[j], o);
  }
  if (cx==0){
    #pragma unroll
    for (int j=0;j<4;j++)
      out[row0 + ry*4 + j] = part[j] + l4b[0];
  }
}

extern "C" void kernel_launch(void* const* d_in, const int* in_sizes, int n_in,
                              void* d_out, int out_size) {
  const float* x    = (const float*)d_in[0];
  const float* emb1 = (const float*)d_in[1];
  const float* emb2 = (const float*)d_in[2];
  const float* gc_w1= (const float*)d_in[3];
  const float* gc_b1= (const float*)d_in[4];
  const float* gc_w2= (const float*)d_in[5];
  const float* gc_b2= (const float*)d_in[6];
  const float* sk0w = (const float*)d_in[7];
  const float* sk0b = (const float*)d_in[8];
  const float* sk1w = (const float*)d_in[9];
  const float* sk1b = (const float*)d_in[10];
  const float* e1w  = (const float*)d_in[11];
  const float* e1b  = (const float*)d_in[12];
  const float* lsw  = (const float*)d_in[13];
  const float* lsb  = (const float*)d_in[14];
  const float* ltw  = (const float*)d_in[15];
  const float* ltb  = (const float*)d_in[16];
  const float* l1w  = (const float*)d_in[17];
  const float* l1b  = (const float*)d_in[18];
  const float* l2w  = (const float*)d_in[19];
  const float* l2b  = (const float*)d_in[20];
  const float* l3w  = (const float*)d_in[21];
  const float* l3b  = (const float*)d_in[22];
  const float* l4w  = (const float*)d_in[23];
  const float* l4b  = (const float*)d_in[24];
  const float* msgw = (const float*)d_in[25];
  const float* msgb = (const float*)d_in[26];
  const float* gatew= (const float*)d_in[27];
  const float* gateb= (const float*)d_in[28];
  const float* lnw  = (const float*)d_in[29];
  const float* lnb  = (const float*)d_in[30];
  float* out = (float*)d_out;

  const int SM1  = (64*97*3 + 96*97*3)*4;  // k_gemm1
  const int SMXG = (64*97*2)*4;            // k_gemm_xg / k_l34
  const int SME1 = (64*97 + 96*97)*4;      // k_e1
  cudaFuncSetAttribute(k_gemm1,   cudaFuncAttributeMaxDynamicSharedMemorySize, SM1);
  cudaFuncSetAttribute(k_gemm_xg, cudaFuncAttributeMaxDynamicSharedMemorySize, SMXG);
  cudaFuncSetAttribute(k_e1,      cudaFuncAttributeMaxDynamicSharedMemorySize, SME1);
  cudaFuncSetAttribute(k_l34,     cudaFuncAttributeMaxDynamicSharedMemorySize, SMXG);

  // graph construction
  k_nv<<<(NNODE*DNODE+255)/256, 256>>>(emb1, gc_w1, gc_b1, 0);
  k_nv<<<(NNODE*DNODE+255)/256, 256>>>(emb2, gc_w2, gc_b2, 1);
  k_adj<<<dim3(NNODE/16, NNODE/16), dim3(16,16)>>>();
  k_topk<<<NNODE, 256>>>();
  k_zero<<<(NNODE+255)/256, 256>>>();
  k_count<<<(NNODE*KE+255)/256, 256>>>();
  k_scan<<<1, 1024>>>();
  k_fill<<<(NNODE*KE+255)/256, 256>>>();
  // decomposition + main GEMMs
  k_decomp<<<NROWS/4, dim3(TT,4)>>>(x);
  k_gemm1<<<NROWS/64, 256, SM1>>>(x, sk0w, sk0b, lsw, lsb, ltw, ltb);
  k_gemm_xg<<<NROWS/64, 256, SMXG>>>(l1w, l1b, sk1w, sk1b);
  k_hg<<<NROWS/8, 256>>>(msgw, msgb, gatew, gateb);
  k_agg<<<dim3(NNODE/16, NB), 256>>>();
  k_gemm_lin2<<<NROWS/64, 256>>>(l2w, l2b, x);
  k_stats<<<1, 1024>>>();
  k_e1<<<NROWS/64, 256, SME1>>>(e1w, e1b, lnw, lnb);
  k_l34<<<NROWS/64, 256, SMXG>>>(l3w, l3b, l4w, l4b, out);
}